// round 8
// baseline (speedup 1.0000x reference)
#include <cuda_runtime.h>
#include <math.h>
#include <stdint.h>

#define LSEQ 1024
#define BATCH 8
#define HDIM 300
#define NC 11234
#define W1COLS 650
#define NPAIR (BATCH * NC)

// ---------------- device scratch ----------------
__device__ __align__(16) float g_A[BATCH * LSEQ * HDIM];
__device__ __align__(16) float g_C[BATCH * LSEQ * HDIM];
__device__ __align__(16) float g_T2[11 * HDIM];

// ---------------- T2 table: M[11,50] = band-kernel sum, then M @ W1[:,600:650]^T
// grid = 11 blocks (one per rel r), 320 threads
__global__ __launch_bounds__(320) void t2_kernel(
    const float* __restrict__ posW, const float* __restrict__ W1,
    const float* __restrict__ b1)
{
    __shared__ float sM[50];
    const int r = blockIdx.x;
    const int tid = threadIdx.x;
    if (tid < 50) {
        float acc = 0.f;
#pragma unroll
        for (int rp = 0; rp < 11; rp++) {
            float d = (float)(r - rp);
            int aa = rp - 5; if (aa < 0) aa = -aa;
            acc += (float)(LSEQ - aa) * expf(-d * d) * posW[rp * 50 + tid];
        }
        sM[tid] = acc;
    }
    __syncthreads();
    if (tid < HDIM) {
        float acc = b1[tid];
        const float* w1row = W1 + tid * W1COLS + 600;
#pragma unroll 5
        for (int d = 0; d < 50; d++) acc += sM[d] * w1row[d];
        g_T2[r * HDIM + tid] = acc;
    }
}

// ---------------- 3-stage cp.async tf32 GEMM with fused h_share add ----------------
#define GBM 128
#define GBN 64
#define GBK 16
#define KSTR 20
#define NIT 19
#define NSTG 3
#define ABUF (GBM * KSTR)          // 2560 floats per stage
#define BBUF (GBN * KSTR)          // 1280 floats per stage
#define SMEM_BYTES ((2 * NSTG * ABUF + NSTG * BBUF) * 4)   // 76800

__device__ __forceinline__ void cp_async16(uint32_t dst, const void* src, int src_bytes) {
    asm volatile("cp.async.cg.shared.global [%0], [%1], 16, %2;\n"
                 :: "r"(dst), "l"(src), "r"(src_bytes));
}
__device__ __forceinline__ void cp_async8(uint32_t dst, const void* src, int src_bytes) {
    asm volatile("cp.async.ca.shared.global [%0], [%1], 8, %2;\n"
                 :: "r"(dst), "l"(src), "r"(src_bytes));
}

__global__ __launch_bounds__(256) void gemm_tf32_kernel(
    const float* __restrict__ h_e, const float* __restrict__ h_c,
    const float* __restrict__ h_share, const float* __restrict__ W1)
{
    extern __shared__ __align__(16) float smem[];
    float* sAe = smem;                       // [NSTG][GBM][KSTR]
    float* sAs = smem + NSTG * ABUF;         // [NSTG][GBM][KSTR]
    float* sB  = smem + 2 * NSTG * ABUF;     // [NSTG][GBN][KSTR]

    const int z = blockIdx.z;
    const float* X = z ? h_c : h_e;
    const int off = z ? 300 : 0;
    float* Out = z ? g_C : g_A;

    const int m0 = blockIdx.y * GBM;
    const int n0 = blockIdx.x * GBN;
    const int tid = threadIdx.x;
    const int warp = tid >> 5;
    const int lane = tid & 31;
    const int wm = (warp & 3) * 32;
    const int wn = (warp >> 2) * 32;
    const int lq = lane >> 2;
    const int lr = lane & 3;

    const int arow = tid >> 2;               // 0..63 (+64)
    const int ak   = (tid & 3) * 4;
    const int brow = tid >> 3;               // 0..31 (+32)
    const int bk   = 2 * (tid & 7);

    const float* eSrc0 = X + (m0 + arow) * HDIM + ak;
    const float* eSrc1 = X + (m0 + arow + 64) * HDIM + ak;
    const float* sSrc0 = h_share + (m0 + arow) * HDIM + ak;
    const float* sSrc1 = h_share + (m0 + arow + 64) * HDIM + ak;
    const float* bSrc0 = W1 + (n0 + brow) * W1COLS + off + bk;
    const float* bSrc1 = W1 + (n0 + brow + 32) * W1COLS + off + bk;
    const bool bOk0 = (n0 + brow) < HDIM;
    const bool bOk1 = (n0 + brow + 32) < HDIM;

    const uint32_t eD0 = (uint32_t)__cvta_generic_to_shared(&sAe[arow * KSTR + ak]);
    const uint32_t eD1 = (uint32_t)__cvta_generic_to_shared(&sAe[(arow + 64) * KSTR + ak]);
    const uint32_t sD0 = (uint32_t)__cvta_generic_to_shared(&sAs[arow * KSTR + ak]);
    const uint32_t sD1 = (uint32_t)__cvta_generic_to_shared(&sAs[(arow + 64) * KSTR + ak]);
    const uint32_t bD0 = (uint32_t)__cvta_generic_to_shared(&sB[brow * KSTR + bk]);
    const uint32_t bD1 = (uint32_t)__cvta_generic_to_shared(&sB[(brow + 32) * KSTR + bk]);
    const uint32_t aBufSz = ABUF * 4;
    const uint32_t bBufSz = BBUF * 4;

    float acc[2][4][4];
#pragma unroll
    for (int a = 0; a < 2; a++)
#pragma unroll
        for (int b = 0; b < 4; b++)
#pragma unroll
            for (int c = 0; c < 4; c++) acc[a][b][c] = 0.f;

    auto issue = [&](int stage, int k0) {
        int asz = ((k0 + ak) < HDIM) ? 16 : 0;
        cp_async16(eD0 + stage * aBufSz, eSrc0 + k0, asz);
        cp_async16(eD1 + stage * aBufSz, eSrc1 + k0, asz);
        cp_async16(sD0 + stage * aBufSz, sSrc0 + k0, asz);
        cp_async16(sD1 + stage * aBufSz, sSrc1 + k0, asz);
        bool kOk = (k0 + bk) < HDIM;
        cp_async8(bD0 + stage * bBufSz, bSrc0 + k0, (bOk0 && kOk) ? 8 : 0);
        cp_async8(bD1 + stage * bBufSz, bSrc1 + k0, (bOk1 && kOk) ? 8 : 0);
    };

    issue(0, 0);
    asm volatile("cp.async.commit_group;\n" ::: "memory");
    issue(1, GBK);
    asm volatile("cp.async.commit_group;\n" ::: "memory");

    int buf = 0;
    for (int it = 0; it < NIT; it++) {
        asm volatile("cp.async.wait_group 1;\n" ::: "memory");
        __syncthreads();

        int nx = it + 2;
        if (nx < NIT) issue(nx % NSTG, nx * GBK);
        asm volatile("cp.async.commit_group;\n" ::: "memory");

        const float* Ae = sAe + buf * ABUF;
        const float* As_ = sAs + buf * ABUF;
        const float* Bb = sB + buf * BBUF;
#pragma unroll
        for (int s = 0; s < 2; s++) {
            const int kb = s * 8 + lr;
            unsigned af[2][4];
#pragma unroll
            for (int mf = 0; mf < 2; mf++) {
                const int r0 = (wm + mf * 16 + lq) * KSTR;
                const int r1 = r0 + 8 * KSTR;
                af[mf][0] = __float_as_uint(Ae[r0 + kb]     + As_[r0 + kb]);
                af[mf][1] = __float_as_uint(Ae[r1 + kb]     + As_[r1 + kb]);
                af[mf][2] = __float_as_uint(Ae[r0 + kb + 4] + As_[r0 + kb + 4]);
                af[mf][3] = __float_as_uint(Ae[r1 + kb + 4] + As_[r1 + kb + 4]);
            }
            unsigned bf[4][2];
#pragma unroll
            for (int nf = 0; nf < 4; nf++) {
                const int nr = (wn + nf * 8 + lq) * KSTR;
                bf[nf][0] = __float_as_uint(Bb[nr + kb]);
                bf[nf][1] = __float_as_uint(Bb[nr + kb + 4]);
            }
#pragma unroll
            for (int mf = 0; mf < 2; mf++)
#pragma unroll
                for (int nf = 0; nf < 4; nf++) {
                    asm volatile(
                        "mma.sync.aligned.m16n8k8.row.col.f32.tf32.tf32.f32 "
                        "{%0,%1,%2,%3}, {%4,%5,%6,%7}, {%8,%9}, {%0,%1,%2,%3};\n"
                        : "+f"(acc[mf][nf][0]), "+f"(acc[mf][nf][1]),
                          "+f"(acc[mf][nf][2]), "+f"(acc[mf][nf][3])
                        : "r"(af[mf][0]), "r"(af[mf][1]), "r"(af[mf][2]), "r"(af[mf][3]),
                          "r"(bf[nf][0]), "r"(bf[nf][1]));
                }
        }
        buf = (buf + 1 == NSTG) ? 0 : buf + 1;
    }

#pragma unroll
    for (int mf = 0; mf < 2; mf++) {
        const int row = m0 + wm + mf * 16 + lq;
#pragma unroll
        for (int nf = 0; nf < 4; nf++) {
            const int col = n0 + wn + nf * 8 + 2 * lr;
            if (col < HDIM) {
                *(float2*)&Out[row * HDIM + col] =
                    make_float2(acc[mf][nf][0], acc[mf][nf][1]);
                *(float2*)&Out[(row + 8) * HDIM + col] =
                    make_float2(acc[mf][nf][2], acc[mf][nf][3]);
            }
        }
    }
}

// ---------------- epilogue: i-tiled, smem row reuse (unchanged from R7) ----------------
#define CHI 8

__device__ __forceinline__ int band_off(int i) {
    if (i <= 1019) return (i < 5) ? (i * i + 11 * i) / 2 : 11 * i - 15;
    int s = i - 1019;
    return 11194 + 10 * s - s * (s - 1) / 2;
}

__global__ __launch_bounds__(256) void epi_kernel(
    const float* __restrict__ lng, const float* __restrict__ lnb,
    const float* __restrict__ W2, const float* __restrict__ b2,
    float* __restrict__ out, int write_pos)
{
    __shared__ __align__(16) float s_g[304];
    __shared__ __align__(16) float s_b[304];
    __shared__ __align__(16) float s_w[304];
    __shared__ __align__(16) float sA[CHI * HDIM];
    __shared__ __align__(16) float sC[(CHI + 10) * HDIM];

    const int tid = threadIdx.x;
    const int i0 = blockIdx.x * CHI;
    const int b = blockIdx.y;

    for (int h = tid; h < HDIM; h += 256) {
        s_g[h] = lng[h]; s_b[h] = lnb[h]; s_w[h] = W2[h];
    }
    {
        const float4* src = (const float4*)(g_A + (b * LSEQ + i0) * HDIM);
        float4* dst = (float4*)sA;
        for (int q = tid; q < CHI * (HDIM / 4); q += 256) dst[q] = src[q];
    }
    const int j0c = (i0 - 5 < 0) ? 0 : i0 - 5;
    const int j1c = (i0 + CHI + 4 > LSEQ - 1) ? LSEQ - 1 : i0 + CHI + 4;
    const int ncr = j1c - j0c + 1;
    {
        const float4* src = (const float4*)(g_C + (b * LSEQ + j0c) * HDIM);
        float4* dst = (float4*)sC;
        for (int q = tid; q < ncr * (HDIM / 4); q += 256) dst[q] = src[q];
    }
    __syncthreads();

    const int warp = tid >> 5;
    const int lane = tid & 31;
    const float bias = __ldg(b2);
    const float inv = 1.f / (float)HDIM;

    for (int it = 0; it < 11; it++) {
        int p = warp + it * 8;
        int i_off = p / 11;
        int rel = p - i_off * 11 - 5;
        int i = i0 + i_off;
        int j = i + rel;
        if (j < 0 || j >= LSEQ) continue;

        const float4* a4 = (const float4*)(sA + i_off * HDIM);
        const float4* c4 = (const float4*)(sC + (j - j0c) * HDIM);
        const float4* t4 = (const float4*)(g_T2 + (rel + 5) * HDIM);

        float4 v[3];
        float s1 = 0.f, s2 = 0.f;
#pragma unroll
        for (int q = 0; q < 3; q++) {
            int f = q * 32 + lane;
            float4 x = make_float4(0.f, 0.f, 0.f, 0.f);
            if (f < 75) {
                float4 a = a4[f], c = c4[f], t = __ldg(&t4[f]);
                x.x = a.x + c.x + t.x; x.y = a.y + c.y + t.y;
                x.z = a.z + c.z + t.z; x.w = a.w + c.w + t.w;
            }
            v[q] = x;
            s1 += x.x + x.y + x.z + x.w;
            s2 += x.x * x.x + x.y * x.y + x.z * x.z + x.w * x.w;
        }
#pragma unroll
        for (int o = 16; o; o >>= 1) {
            s1 += __shfl_xor_sync(0xffffffffu, s1, o);
            s2 += __shfl_xor_sync(0xffffffffu, s2, o);
        }
        float mu = s1 * inv;
        float var = s2 * inv - mu * mu;
        float rstd = rsqrtf(var + 1e-5f);

        float dot = 0.f;
#pragma unroll
        for (int q = 0; q < 3; q++) {
            int f = q * 32 + lane;
            if (f < 75) {
                float4 g = *(const float4*)&s_g[f * 4];
                float4 bb = *(const float4*)&s_b[f * 4];
                float4 w = *(const float4*)&s_w[f * 4];
                float xe[4] = {v[q].x, v[q].y, v[q].z, v[q].w};
                float ge[4] = {g.x, g.y, g.z, g.w};
                float be[4] = {bb.x, bb.y, bb.z, bb.w};
                float we[4] = {w.x, w.y, w.z, w.w};
#pragma unroll
                for (int e = 0; e < 4; e++) {
                    float y = (xe[e] - mu) * rstd * ge[e] + be[e];
                    y = (y > 0.f) ? y : (__expf(y) - 1.f);
                    dot += y * we[e];
                }
            }
        }
#pragma unroll
        for (int o = 16; o; o >>= 1) dot += __shfl_xor_sync(0xffffffffu, dot, o);

        if (lane == 0) {
            int jlo = (i - 5 < 0) ? 0 : i - 5;
            int oidx = band_off(i) + (j - jlo);
            out[b * NC + oidx] = dot + bias;
            if (write_pos && b == 0) {
                out[NPAIR + 2 * oidx]     = (float)(i + 1);
                out[NPAIR + 2 * oidx + 1] = (float)(j + 1);
            }
        }
    }
}

// ---------------- launcher ----------------
extern "C" void kernel_launch(void* const* d_in, const int* in_sizes, int n_in,
                              void* d_out, int out_size) {
    const float* h_e     = (const float*)d_in[0];
    const float* h_c     = (const float*)d_in[1];
    const float* h_share = (const float*)d_in[2];
    const float* pos_W   = (const float*)d_in[4];
    const float* W1      = (const float*)d_in[5];
    const float* b1      = (const float*)d_in[6];
    const float* ln_g    = (const float*)d_in[7];
    const float* ln_b    = (const float*)d_in[8];
    const float* W2      = (const float*)d_in[9];
    const float* b2      = (const float*)d_in[10];
    float* out = (float*)d_out;

    static bool attr_done = false;
    if (!attr_done) {
        cudaFuncSetAttribute(gemm_tf32_kernel,
                             cudaFuncAttributeMaxDynamicSharedMemorySize, SMEM_BYTES);
        attr_done = true;
    }

    t2_kernel<<<11, 320>>>(pos_W, W1, b1);

    dim3 ggrid((HDIM + GBN - 1) / GBN, (BATCH * LSEQ) / GBM, 2);
    gemm_tf32_kernel<<<ggrid, 256, SMEM_BYTES>>>(h_e, h_c, h_share, W1);

    int write_pos = (out_size >= NPAIR + 2 * NC) ? 1 : 0;
    dim3 egrid(LSEQ / CHI, BATCH);
    epi_kernel<<<egrid, 256>>>(ln_g, ln_b, W2, b2, out, write_pos);
}

// round 9
// speedup vs baseline: 1.2020x; 1.2020x over previous
#include <cuda_runtime.h>
#include <math.h>
#include <stdint.h>

#define LSEQ 1024
#define BATCH 8
#define HDIM 300
#define NC 11234
#define W1COLS 650
#define NPAIR (BATCH * NC)

// ---------------- device scratch ----------------
__device__ __align__(16) float g_A[BATCH * LSEQ * HDIM];
__device__ __align__(16) float g_C[BATCH * LSEQ * HDIM];
__device__ __align__(16) float g_He[BATCH * LSEQ * HDIM];
__device__ __align__(16) float g_Hc[BATCH * LSEQ * HDIM];
__device__ __align__(16) float g_T2[11 * HDIM];

// ---------------- prep: adds (8 float4/thread) + T2 table ----------------
__global__ __launch_bounds__(256) void prep_kernel(
    const float* __restrict__ h_e, const float* __restrict__ h_c,
    const float* __restrict__ h_share,
    const float* __restrict__ posW, const float* __restrict__ W1,
    const float* __restrict__ b1)
{
    const int tid = threadIdx.x;
    // N4 = 614400 = 300 blocks * 256 threads * 8 float4 — exact
    const int t0 = blockIdx.x * 2048 + tid;
#pragma unroll
    for (int batch = 0; batch < 2; batch++) {
        const int base = t0 + batch * 1024;
        float4 s[4], a[4], c[4];
#pragma unroll
        for (int k = 0; k < 4; k++) {
            int idx = base + k * 256;
            s[k] = ((const float4*)h_share)[idx];
            a[k] = ((const float4*)h_e)[idx];
            c[k] = ((const float4*)h_c)[idx];
        }
#pragma unroll
        for (int k = 0; k < 4; k++) {
            int idx = base + k * 256;
            float4 ae, ce;
            ae.x = a[k].x + s[k].x; ae.y = a[k].y + s[k].y;
            ae.z = a[k].z + s[k].z; ae.w = a[k].w + s[k].w;
            ce.x = c[k].x + s[k].x; ce.y = c[k].y + s[k].y;
            ce.z = c[k].z + s[k].z; ce.w = c[k].w + s[k].w;
            ((float4*)g_He)[idx] = ae;
            ((float4*)g_Hc)[idx] = ce;
        }
    }

    int gid = blockIdx.x * 256 + tid;
    if (gid < 11 * HDIM) {
        int r = gid / HDIM;
        int h = gid % HDIM;
        float w[11];
#pragma unroll
        for (int rp = 0; rp < 11; rp++) {
            float d = (float)(r - rp);
            int aa = rp - 5; if (aa < 0) aa = -aa;
            w[rp] = (float)(LSEQ - aa) * expf(-d * d);
        }
        float acc = b1[h];
        const float* w1row = W1 + h * W1COLS + 600;
#pragma unroll 2
        for (int d = 0; d < 50; d++) {
            float tv = 0.f;
#pragma unroll
            for (int rp = 0; rp < 11; rp++) tv += w[rp] * posW[rp * 50 + d];
            acc += tv * w1row[d];
        }
        g_T2[gid] = acc;
    }
}

// ---------------- 3-stage cp.async pipelined tf32 GEMM (R7 known-good) ----------------
#define GBM 128
#define GBN 64
#define GBK 16
#define KSTR 20
#define NIT 19
#define NSTG 3

__device__ __forceinline__ void cp_async16(uint32_t dst, const void* src, int src_bytes) {
    asm volatile("cp.async.cg.shared.global [%0], [%1], 16, %2;\n"
                 :: "r"(dst), "l"(src), "r"(src_bytes));
}
__device__ __forceinline__ void cp_async8(uint32_t dst, const void* src, int src_bytes) {
    asm volatile("cp.async.ca.shared.global [%0], [%1], 8, %2;\n"
                 :: "r"(dst), "l"(src), "r"(src_bytes));
}

__global__ __launch_bounds__(256) void gemm_tf32_kernel(const float* __restrict__ W1)
{
    __shared__ __align__(16) float As[NSTG][GBM][KSTR];
    __shared__ __align__(16) float Bs[NSTG][GBN][KSTR];

    const int z = blockIdx.z;
    const float* X = z ? g_Hc : g_He;
    const int off = z ? 300 : 0;
    float* Out = z ? g_C : g_A;

    const int m0 = blockIdx.y * GBM;
    const int n0 = blockIdx.x * GBN;
    const int tid = threadIdx.x;
    const int warp = tid >> 5;
    const int lane = tid & 31;
    const int wm = (warp & 3) * 32;
    const int wn = (warp >> 2) * 32;
    const int lq = lane >> 2;
    const int lr = lane & 3;

    const int arow = tid >> 2;
    const int ak   = (tid & 3) * 4;
    const int brow = tid >> 3;
    const int bk   = 2 * (tid & 7);

    const float* aSrc0 = X + (m0 + arow) * HDIM + ak;
    const float* aSrc1 = X + (m0 + arow + 64) * HDIM + ak;
    const float* bSrc0 = W1 + (n0 + brow) * W1COLS + off + bk;
    const float* bSrc1 = W1 + (n0 + brow + 32) * W1COLS + off + bk;
    const bool bOk0 = (n0 + brow) < HDIM;
    const bool bOk1 = (n0 + brow + 32) < HDIM;

    const uint32_t aD0 = (uint32_t)__cvta_generic_to_shared(&As[0][arow][ak]);
    const uint32_t aD1 = (uint32_t)__cvta_generic_to_shared(&As[0][arow + 64][ak]);
    const uint32_t bD0 = (uint32_t)__cvta_generic_to_shared(&Bs[0][brow][bk]);
    const uint32_t bD1 = (uint32_t)__cvta_generic_to_shared(&Bs[0][brow + 32][bk]);
    const uint32_t aBufSz = GBM * KSTR * 4;
    const uint32_t bBufSz = GBN * KSTR * 4;

    float acc[2][4][4];
#pragma unroll
    for (int a = 0; a < 2; a++)
#pragma unroll
        for (int b = 0; b < 4; b++)
#pragma unroll
            for (int c = 0; c < 4; c++) acc[a][b][c] = 0.f;

    auto issue = [&](int stage, int k0) {
        int asz = ((k0 + ak) < HDIM) ? 16 : 0;
        cp_async16(aD0 + stage * aBufSz, aSrc0 + k0, asz);
        cp_async16(aD1 + stage * aBufSz, aSrc1 + k0, asz);
        bool kOk = (k0 + bk) < HDIM;
        cp_async8(bD0 + stage * bBufSz, bSrc0 + k0, (bOk0 && kOk) ? 8 : 0);
        cp_async8(bD1 + stage * bBufSz, bSrc1 + k0, (bOk1 && kOk) ? 8 : 0);
    };

    issue(0, 0);
    asm volatile("cp.async.commit_group;\n" ::: "memory");
    issue(1, GBK);
    asm volatile("cp.async.commit_group;\n" ::: "memory");

    int buf = 0;
    for (int it = 0; it < NIT; it++) {
        asm volatile("cp.async.wait_group 1;\n" ::: "memory");
        __syncthreads();

        int nx = it + 2;
        if (nx < NIT) issue(nx % NSTG, nx * GBK);
        asm volatile("cp.async.commit_group;\n" ::: "memory");

#pragma unroll
        for (int s = 0; s < 2; s++) {
            const int kb = s * 8 + lr;
            unsigned af[2][4];
#pragma unroll
            for (int mf = 0; mf < 2; mf++) {
                const int mrow = wm + mf * 16 + lq;
                af[mf][0] = __float_as_uint(As[buf][mrow][kb]);
                af[mf][1] = __float_as_uint(As[buf][mrow + 8][kb]);
                af[mf][2] = __float_as_uint(As[buf][mrow][kb + 4]);
                af[mf][3] = __float_as_uint(As[buf][mrow + 8][kb + 4]);
            }
            unsigned bf[4][2];
#pragma unroll
            for (int nf = 0; nf < 4; nf++) {
                const int nrow = wn + nf * 8 + lq;
                bf[nf][0] = __float_as_uint(Bs[buf][nrow][kb]);
                bf[nf][1] = __float_as_uint(Bs[buf][nrow][kb + 4]);
            }
#pragma unroll
            for (int mf = 0; mf < 2; mf++)
#pragma unroll
                for (int nf = 0; nf < 4; nf++) {
                    asm volatile(
                        "mma.sync.aligned.m16n8k8.row.col.f32.tf32.tf32.f32 "
                        "{%0,%1,%2,%3}, {%4,%5,%6,%7}, {%8,%9}, {%0,%1,%2,%3};\n"
                        : "+f"(acc[mf][nf][0]), "+f"(acc[mf][nf][1]),
                          "+f"(acc[mf][nf][2]), "+f"(acc[mf][nf][3])
                        : "r"(af[mf][0]), "r"(af[mf][1]), "r"(af[mf][2]), "r"(af[mf][3]),
                          "r"(bf[nf][0]), "r"(bf[nf][1]));
                }
        }
        buf = (buf + 1 == NSTG) ? 0 : buf + 1;
    }

#pragma unroll
    for (int mf = 0; mf < 2; mf++) {
        const int row = m0 + wm + mf * 16 + lq;
#pragma unroll
        for (int nf = 0; nf < 4; nf++) {
            const int col = n0 + wn + nf * 8 + 2 * lr;
            if (col < HDIM) {
                *(float2*)&Out[row * HDIM + col] =
                    make_float2(acc[mf][nf][0], acc[mf][nf][1]);
                *(float2*)&Out[(row + 8) * HDIM + col] =
                    make_float2(acc[mf][nf][2], acc[mf][nf][3]);
            }
        }
    }
}

// ---------------- epilogue v4: i-tiled, 16-lane segments (2 pairs/warp) ----------------
#define CHI 8

__device__ __forceinline__ int band_off(int i) {
    if (i <= 1019) return (i < 5) ? (i * i + 11 * i) / 2 : 11 * i - 15;
    int s = i - 1019;
    return 11194 + 10 * s - s * (s - 1) / 2;
}

__global__ __launch_bounds__(256) void epi_kernel(
    const float* __restrict__ lng, const float* __restrict__ lnb,
    const float* __restrict__ W2, const float* __restrict__ b2,
    float* __restrict__ out, int write_pos)
{
    __shared__ __align__(16) float s_g[304];
    __shared__ __align__(16) float s_b[304];
    __shared__ __align__(16) float s_w[304];
    __shared__ __align__(16) float sT2[11 * HDIM];        // 13.2 KB
    __shared__ __align__(16) float sA[CHI * HDIM];        // 9.6 KB
    __shared__ __align__(16) float sC[(CHI + 10) * HDIM]; // 21.6 KB

    const int tid = threadIdx.x;
    const int i0 = blockIdx.x * CHI;
    const int b = blockIdx.y;

    for (int h = tid; h < HDIM; h += 256) {
        s_g[h] = lng[h]; s_b[h] = lnb[h]; s_w[h] = W2[h];
    }
    for (int q = tid; q < 11 * HDIM / 4; q += 256)
        ((float4*)sT2)[q] = ((const float4*)g_T2)[q];
    {
        const float4* src = (const float4*)(g_A + (b * LSEQ + i0) * HDIM);
        float4* dst = (float4*)sA;
        for (int q = tid; q < CHI * (HDIM / 4); q += 256) dst[q] = src[q];
    }
    const int j0c = (i0 - 5 < 0) ? 0 : i0 - 5;
    const int j1c = (i0 + CHI + 4 > LSEQ - 1) ? LSEQ - 1 : i0 + CHI + 4;
    const int ncr = j1c - j0c + 1;
    {
        const float4* src = (const float4*)(g_C + (b * LSEQ + j0c) * HDIM);
        float4* dst = (float4*)sC;
        for (int q = tid; q < ncr * (HDIM / 4); q += 256) dst[q] = src[q];
    }
    __syncthreads();

    const int warp = tid >> 5;
    const int lane = tid & 31;
    const int half = lane >> 4;      // 0/1: which pair within warp
    const int l16 = lane & 15;
    const float bias = __ldg(b2);
    const float inv = 1.f / (float)HDIM;

    // 88 pairs per block; 16 pair-slots per iteration (8 warps x 2 halves)
    for (int it = 0; it < 6; it++) {
        int p = it * 16 + warp * 2 + half;   // 0..95
        bool pv = (p < 88);
        int pc = pv ? p : 0;
        int i_off = pc / 11;
        int rel = pc - i_off * 11 - 5;
        int i = i0 + i_off;
        int j = i + rel;
        pv = pv && (j >= 0) && (j < LSEQ);

        const float4* a4 = (const float4*)(sA + i_off * HDIM);
        const float4* c4 = (const float4*)(sC + (pv ? (j - j0c) : 0) * HDIM);
        const float4* t4 = (const float4*)(sT2 + (rel + 5) * HDIM);

        float s1 = 0.f, s2 = 0.f;
#pragma unroll
        for (int q = 0; q < 5; q++) {
            int f = q * 16 + l16;            // 0..79
            if (f < 75) {
                float4 a = a4[f], c = c4[f], t = t4[f];
                float x0 = a.x + c.x + t.x, x1 = a.y + c.y + t.y;
                float x2 = a.z + c.z + t.z, x3 = a.w + c.w + t.w;
                s1 += x0 + x1 + x2 + x3;
                s2 += x0 * x0 + x1 * x1 + x2 * x2 + x3 * x3;
            }
        }
#pragma unroll
        for (int o = 8; o; o >>= 1) {
            s1 += __shfl_xor_sync(0xffffffffu, s1, o);
            s2 += __shfl_xor_sync(0xffffffffu, s2, o);
        }
        float mu = s1 * inv;
        float var = s2 * inv - mu * mu;
        float rstd = rsqrtf(var + 1e-5f);

        float dot = 0.f;
#pragma unroll
        for (int q = 0; q < 5; q++) {
            int f = q * 16 + l16;
            if (f < 75) {
                float4 a = a4[f], c = c4[f], t = t4[f];
                float4 g = *(const float4*)&s_g[f * 4];
                float4 bb = *(const float4*)&s_b[f * 4];
                float4 w = *(const float4*)&s_w[f * 4];
                float xe[4] = {a.x + c.x + t.x, a.y + c.y + t.y,
                               a.z + c.z + t.z, a.w + c.w + t.w};
                float ge[4] = {g.x, g.y, g.z, g.w};
                float be[4] = {bb.x, bb.y, bb.z, bb.w};
                float we[4] = {w.x, w.y, w.z, w.w};
#pragma unroll
                for (int e = 0; e < 4; e++) {
                    float y = (xe[e] - mu) * rstd * ge[e] + be[e];
                    y = (y > 0.f) ? y : (__expf(y) - 1.f);
                    dot += y * we[e];
                }
            }
        }
#pragma unroll
        for (int o = 8; o; o >>= 1) dot += __shfl_xor_sync(0xffffffffu, dot, o);

        if (pv && l16 == 0) {
            int jlo = (i - 5 < 0) ? 0 : i - 5;
            int oidx = band_off(i) + (j - jlo);
            out[b * NC + oidx] = dot + bias;
            if (write_pos && b == 0) {
                out[NPAIR + 2 * oidx]     = (float)(i + 1);
                out[NPAIR + 2 * oidx + 1] = (float)(j + 1);
            }
        }
    }
}

// ---------------- launcher ----------------
extern "C" void kernel_launch(void* const* d_in, const int* in_sizes, int n_in,
                              void* d_out, int out_size) {
    const float* h_e     = (const float*)d_in[0];
    const float* h_c     = (const float*)d_in[1];
    const float* h_share = (const float*)d_in[2];
    const float* pos_W   = (const float*)d_in[4];
    const float* W1      = (const float*)d_in[5];
    const float* b1      = (const float*)d_in[6];
    const float* ln_g    = (const float*)d_in[7];
    const float* ln_b    = (const float*)d_in[8];
    const float* W2      = (const float*)d_in[9];
    const float* b2      = (const float*)d_in[10];
    float* out = (float*)d_out;

    prep_kernel<<<300, 256>>>(h_e, h_c, h_share, pos_W, W1, b1);

    dim3 ggrid((HDIM + GBN - 1) / GBN, (BATCH * LSEQ) / GBM, 2);
    gemm_tf32_kernel<<<ggrid, 256>>>(W1);

    int write_pos = (out_size >= NPAIR + 2 * NC) ? 1 : 0;
    dim3 egrid(LSEQ / CHI, BATCH);
    epi_kernel<<<egrid, 256>>>(ln_g, ln_b, W2, b2, out, write_pos);
}